// round 8
// baseline (speedup 1.0000x reference)
#include <cuda_runtime.h>
#include <cstdint>
#include <cstddef>

#define D_MODEL 1024
#define N_HEADS 16
#define HEAD_DIM 64
#define BATCH 4
#define SEQ 2048
#define QKV_STRIDE (3 * D_MODEL)

// ------------------------------ scratch ------------------------------------
__device__ float g_qkv[(size_t)BATCH * SEQ * QKV_STRIDE];    // [b,t,3072] (tf32, q pre-scaled)
__device__ float g_attn[(size_t)BATCH * SEQ * D_MODEL];      // [b,t,1024] (tf32)
__device__ float g_x32[(size_t)BATCH * SEQ * D_MODEL];       // x, tf32-rounded
__device__ float g_wqkvT[(size_t)3 * D_MODEL * D_MODEL];     // [3072,1024] k-major, tf32
__device__ float g_woT[(size_t)D_MODEL * D_MODEL];           // [1024,1024] k-major, tf32

// ------------------------------ helpers ------------------------------------
__device__ __forceinline__ uint32_t smem_u32(const void* p) {
    uint32_t a;
    asm("{ .reg .u64 t; cvta.to.shared.u64 t, %1; cvt.u32.u64 %0, t; }" : "=r"(a) : "l"(p));
    return a;
}
__device__ __forceinline__ uint32_t f2tf(float x) {
    uint32_t r; asm("cvt.rna.tf32.f32 %0, %1;" : "=r"(r) : "f"(x)); return r;
}
__device__ __forceinline__ void cp16(uint32_t dst, const void* src) {
    asm volatile("cp.async.ca.shared.global [%0], [%1], 16;" :: "r"(dst), "l"(src));
}
#define CP_COMMIT() asm volatile("cp.async.commit_group;" ::: "memory")
#define CP_WAIT0()  asm volatile("cp.async.wait_group 0;" ::: "memory")

__device__ __forceinline__ void ldsm4(uint32_t* r, uint32_t addr) {
    asm volatile("ldmatrix.sync.aligned.m8n8.x4.shared.b16 {%0,%1,%2,%3}, [%4];"
        : "=r"(r[0]), "=r"(r[1]), "=r"(r[2]), "=r"(r[3]) : "r"(addr));
}

// D = A(tf32) * B(tf32) + D ; m16n8k8
__device__ __forceinline__ void mma8(float* c, const uint32_t* a, const uint32_t* b) {
    asm volatile(
        "mma.sync.aligned.m16n8k8.row.col.f32.tf32.tf32.f32 "
        "{%0,%1,%2,%3}, {%4,%5,%6,%7}, {%8,%9}, {%0,%1,%2,%3};"
        : "+f"(c[0]), "+f"(c[1]), "+f"(c[2]), "+f"(c[3])
        : "r"(a[0]), "r"(a[1]), "r"(a[2]), "r"(a[3]), "r"(b[0]), "r"(b[1]));
}

// ------------------------------ init kernels -------------------------------
__global__ void convert_x(const float* __restrict__ in, float* __restrict__ out) {
    size_t i = ((size_t)blockIdx.x * blockDim.x + threadIdx.x) * 4;
    float4 v = *(const float4*)(in + i);
    v.x = __uint_as_float(f2tf(v.x)); v.y = __uint_as_float(f2tf(v.y));
    v.z = __uint_as_float(f2tf(v.z)); v.w = __uint_as_float(f2tf(v.w));
    *(float4*)(out + i) = v;
}

// out[C][R] = tf32(in[R][C])
__global__ void transpose_w(const float* __restrict__ in, float* __restrict__ out,
                            int R, int C) {
    __shared__ float t[32][33];
    int c0 = blockIdx.x * 32, r0 = blockIdx.y * 32;
    #pragma unroll
    for (int j = 0; j < 4; j++) {
        int r = threadIdx.y + j * 8;
        t[r][threadIdx.x] = in[(size_t)(r0 + r) * C + c0 + threadIdx.x];
    }
    __syncthreads();
    #pragma unroll
    for (int j = 0; j < 4; j++) {
        int c = threadIdx.y + j * 8;
        out[(size_t)(c0 + c) * R + r0 + threadIdx.x] =
            __uint_as_float(f2tf(t[threadIdx.x][c]));
    }
}

// ------------------------------ tf32 GEMM ----------------------------------
// C[M,N] = A[M,K] @ BT[N,K]^T + bias[N]. A,BT pre-rounded tf32, k-contiguous.
// 128x128 CTA tile, BK=32, 128 threads / 4 warps, warp tile m64 x n64.
#define TS_STR 36      // 144B rows
#define G_SMEM ((2 * 128 * TS_STR + 2 * 128 * TS_STR) * 4)

template<bool ROUND>
__global__ void __launch_bounds__(128, 2) gemm_mma(
    const float* __restrict__ A, const float* __restrict__ BT,
    const float* __restrict__ bias, float* __restrict__ C,
    int M, int N, int K, int qcols)
{
    extern __shared__ float smf[];
    float* As = smf;                       // [2][128][TS_STR]
    float* Bs = smf + 2 * 128 * TS_STR;    // [2][128][TS_STR]

    const int tid = threadIdx.x;
    const int lane = tid & 31, warp = tid >> 5;
    const int g = lane >> 2, q = lane & 3;
    const int wm = (warp >> 1) * 64, wn = (warp & 1) * 64;
    const int m0 = blockIdx.y * 128, n0 = blockIdx.x * 128;

    // loaders: 1 thread/row, 8x16B per row (32 floats)
    const float* Ag = A + (size_t)(m0 + tid) * K;
    const float* Bg = BT + (size_t)(n0 + tid) * K;
    const uint32_t asU = smem_u32(As), bsU = smem_u32(Bs);
    const uint32_t AsA = asU + tid * TS_STR * 4;
    const uint32_t BsA = bsU + tid * TS_STR * 4;

    // LDSM per-thread source rows/cols
    const int a_r = ((lane >> 3) & 1) * 8 + (lane & 7);
    const int a_c = ((lane >> 4) & 1) * 4;
    const int b_r = ((lane >> 4) & 1) * 8 + (lane & 7);
    const int b_c = ((lane >> 3) & 1) * 4;
    const uint32_t aoff = ((wm + a_r) * TS_STR + a_c) * 4;
    const uint32_t boff = ((wn + b_r) * TS_STR + b_c) * 4;

    float acc[4][8][4];
    #pragma unroll
    for (int i = 0; i < 4; i++)
        #pragma unroll
        for (int j = 0; j < 8; j++)
            #pragma unroll
            for (int t = 0; t < 4; t++) acc[i][j][t] = 0.0f;

    const int nk = K >> 5;

    // prefetch stage 0
    #pragma unroll
    for (int i = 0; i < 8; i++) cp16(AsA + i * 16, Ag + i * 4);
    #pragma unroll
    for (int i = 0; i < 8; i++) cp16(BsA + i * 16, Bg + i * 4);
    CP_COMMIT();

    int buf = 0;
    for (int kt = 0; kt < nk; kt++) {
        CP_WAIT0();
        __syncthreads();
        if (kt + 1 < nk) {
            int s = buf ^ 1;
            const float* ag = Ag + (kt + 1) * 32;
            const float* bg = Bg + (kt + 1) * 32;
            uint32_t ad = AsA + s * 128 * TS_STR * 4;
            uint32_t bd = BsA + s * 128 * TS_STR * 4;
            #pragma unroll
            for (int i = 0; i < 8; i++) cp16(ad + i * 16, ag + i * 4);
            #pragma unroll
            for (int i = 0; i < 8; i++) cp16(bd + i * 16, bg + i * 4);
            CP_COMMIT();
        }
        const uint32_t aB = asU + buf * 128 * TS_STR * 4 + aoff;
        const uint32_t bB = bsU + buf * 128 * TS_STR * 4 + boff;
        #pragma unroll
        for (int kk = 0; kk < 32; kk += 8) {
            uint32_t af[4][4], bf[4][4];
            #pragma unroll
            for (int ip = 0; ip < 4; ip++)
                ldsm4(af[ip], aB + kk * 4 + ip * 16 * TS_STR * 4);
            #pragma unroll
            for (int jp = 0; jp < 4; jp++)
                ldsm4(bf[jp], bB + kk * 4 + jp * 16 * TS_STR * 4);
            #pragma unroll
            for (int ip = 0; ip < 4; ip++)
                #pragma unroll
                for (int jp = 0; jp < 4; jp++) {
                    mma8(acc[ip][2 * jp],     af[ip], &bf[jp][0]);
                    mma8(acc[ip][2 * jp + 1], af[ip], &bf[jp][2]);
                }
        }
        __syncthreads();
        buf ^= 1;
    }

    // epilogue
    #pragma unroll
    for (int i = 0; i < 4; i++) {
        int row = m0 + wm + i * 16 + g;
        #pragma unroll
        for (int j = 0; j < 8; j++) {
            int col = n0 + wn + j * 8 + 2 * q;
            float b0 = __ldg(&bias[col]), b1 = __ldg(&bias[col + 1]);
            float v0 = acc[i][j][0] + b0, v1 = acc[i][j][1] + b1;
            float v2 = acc[i][j][2] + b0, v3 = acc[i][j][3] + b1;
            if (ROUND) {
                float sc = (col < qcols) ? 0.125f : 1.0f;
                v0 = __uint_as_float(f2tf(v0 * sc));
                v1 = __uint_as_float(f2tf(v1 * sc));
                v2 = __uint_as_float(f2tf(v2 * sc));
                v3 = __uint_as_float(f2tf(v3 * sc));
            }
            *(float2*)(C + (size_t)row * N + col) = make_float2(v0, v1);
            *(float2*)(C + (size_t)(row + 8) * N + col) = make_float2(v2, v3);
        }
    }
}

// ------------------------------ attention ----------------------------------
// Flash, BQ=128, BKV=64, 4 warps; warp w owns q-rows [w*32, w*32+32).
// Warp tiles m32n64 for S and PV; V scalar fragments reused across m16 halves.
#define QS_STR 68
#define VS_STR 72
#define A_SMEM ((128 * QS_STR + 64 * QS_STR + 64 * VS_STR + 128 * QS_STR) * 4)

__global__ void __launch_bounds__(128, 2) attn_mma()
{
    extern __shared__ float smf[];
    float* Qs = smf;                   // [128][68] (pre-scaled tf32)
    float* Ks = Qs + 128 * QS_STR;     // [64][68]
    float* Vs = Ks + 64 * QS_STR;      // [64][72]
    float* Ps = Vs + 64 * VS_STR;      // [128][68] warp-private rows

    const int tid = threadIdx.x;
    const int lane = tid & 31, warp = tid >> 5;
    const int g = lane >> 2, q = lane & 3;
    const int qt = gridDim.x - 1 - blockIdx.x;   // heaviest tiles first
    const int q0 = qt * 128;
    const int h = blockIdx.y, b = blockIdx.z;

    const float* base = g_qkv + (size_t)b * SEQ * QKV_STRIDE + h * HEAD_DIM;
    const uint32_t qsU = smem_u32(Qs), ksU = smem_u32(Ks);
    const uint32_t vsU = smem_u32(Vs), psU = smem_u32(Ps);

    // LDSM per-thread source rows/cols
    const int a_r = ((lane >> 3) & 1) * 8 + (lane & 7);
    const int a_c = ((lane >> 4) & 1) * 4;
    const int b_r = ((lane >> 4) & 1) * 8 + (lane & 7);
    const int b_c = ((lane >> 3) & 1) * 4;
    const uint32_t aoffQ = ((warp * 32 + a_r) * QS_STR + a_c) * 4;
    const uint32_t boffK = (b_r * QS_STR + b_c) * 4;

    // load Q tile (128 rows x 64 floats = 2048 cp16 / 128 thr = 16 each)
    #pragma unroll
    for (int jj = 0; jj < 16; jj++) {
        int idx = tid + 128 * jj;
        int row = idx >> 4, c4 = (idx & 15) << 2;
        cp16(qsU + (row * QS_STR + c4) * 4, base + (size_t)(q0 + row) * QKV_STRIDE + c4);
    }
    CP_COMMIT();

    float mr[2][2] = {{-1e30f, -1e30f}, {-1e30f, -1e30f}};
    float lr[2][2] = {{0.0f, 0.0f}, {0.0f, 0.0f}};
    float O[2][8][4];
    #pragma unroll
    for (int i = 0; i < 2; i++)
        #pragma unroll
        for (int j = 0; j < 8; j++)
            #pragma unroll
            for (int t = 0; t < 4; t++) O[i][j][t] = 0.0f;

    const int nkv = 2 * (qt + 1);

    for (int kv = 0; kv < nkv; kv++) {
        const int kv0 = kv * 64;
        __syncthreads();
        // load K,V tiles (64 rows x 64 floats = 1024 cp16 each; 8+8 per thread)
        #pragma unroll
        for (int jj = 0; jj < 8; jj++) {
            int idx = tid + 128 * jj;
            int row = idx >> 4, c4 = (idx & 15) << 2;
            const float* src = base + (size_t)(kv0 + row) * QKV_STRIDE + c4;
            cp16(ksU + (row * QS_STR + c4) * 4, src + D_MODEL);
            cp16(vsU + (row * VS_STR + c4) * 4, src + 2 * D_MODEL);
        }
        CP_COMMIT();
        CP_WAIT0();
        __syncthreads();

        // S = Q K^T  (m32 x n64 per warp, k=64)
        float sacc[2][8][4];
        #pragma unroll
        for (int i = 0; i < 2; i++)
            #pragma unroll
            for (int j = 0; j < 8; j++)
                #pragma unroll
                for (int t = 0; t < 4; t++) sacc[i][j][t] = 0.0f;
        #pragma unroll
        for (int kk = 0; kk < 64; kk += 8) {
            uint32_t af[2][4], bf[4][4];
            ldsm4(af[0], qsU + aoffQ + kk * 4);
            ldsm4(af[1], qsU + aoffQ + kk * 4 + 16 * QS_STR * 4);
            #pragma unroll
            for (int jp = 0; jp < 4; jp++)
                ldsm4(bf[jp], ksU + boffK + kk * 4 + jp * 16 * QS_STR * 4);
            #pragma unroll
            for (int i = 0; i < 2; i++)
                #pragma unroll
                for (int jp = 0; jp < 4; jp++) {
                    mma8(sacc[i][2 * jp],     af[i], &bf[jp][0]);
                    mma8(sacc[i][2 * jp + 1], af[i], &bf[jp][2]);
                }
        }

        // causal mask (diagonal only reachable in last two kv tiles)
        if (kv >= nkv - 2) {
            #pragma unroll
            for (int i = 0; i < 2; i++) {
                int ra = q0 + warp * 32 + i * 16 + g;
                int rb = ra + 8;
                #pragma unroll
                for (int j = 0; j < 8; j++) {
                    int c0 = kv0 + j * 8 + 2 * q;
                    if (c0 > ra)     sacc[i][j][0] = -1e30f;
                    if (c0 + 1 > ra) sacc[i][j][1] = -1e30f;
                    if (c0 > rb)     sacc[i][j][2] = -1e30f;
                    if (c0 + 1 > rb) sacc[i][j][3] = -1e30f;
                }
            }
        }

        // softmax per m16 fragment
        #pragma unroll
        for (int i = 0; i < 2; i++) {
            float mxa = -1e30f, mxb = -1e30f;
            #pragma unroll
            for (int j = 0; j < 8; j++) {
                mxa = fmaxf(mxa, fmaxf(sacc[i][j][0], sacc[i][j][1]));
                mxb = fmaxf(mxb, fmaxf(sacc[i][j][2], sacc[i][j][3]));
            }
            mxa = fmaxf(mxa, __shfl_xor_sync(0xffffffff, mxa, 1));
            mxa = fmaxf(mxa, __shfl_xor_sync(0xffffffff, mxa, 2));
            mxb = fmaxf(mxb, __shfl_xor_sync(0xffffffff, mxb, 1));
            mxb = fmaxf(mxb, __shfl_xor_sync(0xffffffff, mxb, 2));

            float mna = fmaxf(mr[i][0], mxa), mnb = fmaxf(mr[i][1], mxb);
            float aa = __expf(mr[i][0] - mna), ab = __expf(mr[i][1] - mnb);
            mr[i][0] = mna; mr[i][1] = mnb;

            float sa = 0.0f, sb = 0.0f;
            float* prow_a = Ps + (warp * 32 + i * 16 + g) * QS_STR;
            float* prow_b = prow_a + 8 * QS_STR;
            #pragma unroll
            for (int j = 0; j < 8; j++) {
                float p0 = __expf(sacc[i][j][0] - mna);
                float p1 = __expf(sacc[i][j][1] - mna);
                float p2 = __expf(sacc[i][j][2] - mnb);
                float p3 = __expf(sacc[i][j][3] - mnb);
                sa += p0 + p1; sb += p2 + p3;
                int c = j * 8 + 2 * q;
                prow_a[c]     = __uint_as_float(f2tf(p0));
                prow_a[c + 1] = __uint_as_float(f2tf(p1));
                prow_b[c]     = __uint_as_float(f2tf(p2));
                prow_b[c + 1] = __uint_as_float(f2tf(p3));
            }
            sa += __shfl_xor_sync(0xffffffff, sa, 1);
            sa += __shfl_xor_sync(0xffffffff, sa, 2);
            sb += __shfl_xor_sync(0xffffffff, sb, 1);
            sb += __shfl_xor_sync(0xffffffff, sb, 2);
            lr[i][0] = lr[i][0] * aa + sa;
            lr[i][1] = lr[i][1] * ab + sb;
            #pragma unroll
            for (int j = 0; j < 8; j++) {
                O[i][j][0] *= aa; O[i][j][1] *= aa;
                O[i][j][2] *= ab; O[i][j][3] *= ab;
            }
        }
        __syncwarp();   // order Ps stores -> ldmatrix (warp-private rows)

        // O += P @ V  (m32 x n64, k=64); V scalar fragments shared across i
        #pragma unroll
        for (int kk = 0; kk < 64; kk += 8) {
            uint32_t af[2][4];
            ldsm4(af[0], psU + aoffQ + kk * 4);
            ldsm4(af[1], psU + aoffQ + kk * 4 + 16 * QS_STR * 4);
            #pragma unroll
            for (int j = 0; j < 8; j++) {
                const float* pb = Vs + (kk + q) * VS_STR + j * 8 + g;
                uint32_t bf[2] = {__float_as_uint(pb[0]), __float_as_uint(pb[4 * VS_STR])};
                mma8(O[0][j], af[0], bf);
                mma8(O[1][j], af[1], bf);
            }
        }
    }

    // epilogue: normalize, round to tf32, write [b,t,h*64+d]
    #pragma unroll
    for (int i = 0; i < 2; i++) {
        int ra = q0 + warp * 32 + i * 16 + g;
        float inva = 1.0f / lr[i][0], invb = 1.0f / lr[i][1];
        float* outa = g_attn + ((size_t)b * SEQ + ra) * D_MODEL + h * HEAD_DIM;
        float* outb = outa + (size_t)8 * D_MODEL;
        #pragma unroll
        for (int j = 0; j < 8; j++) {
            int c = j * 8 + 2 * q;
            *(float2*)(outa + c) = make_float2(__uint_as_float(f2tf(O[i][j][0] * inva)),
                                               __uint_as_float(f2tf(O[i][j][1] * inva)));
            *(float2*)(outb + c) = make_float2(__uint_as_float(f2tf(O[i][j][2] * invb)),
                                               __uint_as_float(f2tf(O[i][j][3] * invb)));
        }
    }
}

// ---------------------------------------------------------------------------
extern "C" void kernel_launch(void* const* d_in, const int* in_sizes, int n_in,
                              void* d_out, int out_size)
{
    (void)in_sizes; (void)n_in; (void)out_size;
    const float* x     = (const float*)d_in[0];
    const float* w_qkv = (const float*)d_in[1];
    const float* b_qkv = (const float*)d_in[2];
    const float* w_out = (const float*)d_in[3];
    const float* b_out = (const float*)d_in[4];
    float* out = (float*)d_out;

    float *qkv, *attn, *x32, *wqkvT, *woT;
    cudaGetSymbolAddress((void**)&qkv, g_qkv);
    cudaGetSymbolAddress((void**)&attn, g_attn);
    cudaGetSymbolAddress((void**)&x32, g_x32);
    cudaGetSymbolAddress((void**)&wqkvT, g_wqkvT);
    cudaGetSymbolAddress((void**)&woT, g_woT);

    cudaFuncSetAttribute(gemm_mma<true>,  cudaFuncAttributeMaxDynamicSharedMemorySize, G_SMEM);
    cudaFuncSetAttribute(gemm_mma<false>, cudaFuncAttributeMaxDynamicSharedMemorySize, G_SMEM);
    cudaFuncSetAttribute(attn_mma, cudaFuncAttributeMaxDynamicSharedMemorySize, A_SMEM);

    const int M = BATCH * SEQ;  // 8192

    // init: tf32-round x, transpose+round weights
    convert_x<<<(M * D_MODEL) / (256 * 4), 256>>>(x, x32);
    transpose_w<<<dim3(3 * D_MODEL / 32, D_MODEL / 32), dim3(32, 8)>>>(w_qkv, wqkvT, D_MODEL, 3 * D_MODEL);
    transpose_w<<<dim3(D_MODEL / 32, D_MODEL / 32), dim3(32, 8)>>>(w_out, woT, D_MODEL, D_MODEL);

    // 1) QKV projection (writes tf32, q-cols pre-scaled by 0.125)
    gemm_mma<true><<<dim3(3 * D_MODEL / 128, M / 128), 128, G_SMEM>>>(
        x32, wqkvT, b_qkv, qkv, M, 3 * D_MODEL, D_MODEL, D_MODEL);

    // 2) causal flash attention
    attn_mma<<<dim3(SEQ / 128, N_HEADS, BATCH), 128, A_SMEM>>>();

    // 3) output projection (full fp32 out)
    gemm_mma<false><<<dim3(D_MODEL / 128, M / 128), 128, G_SMEM>>>(
        attn, woT, b_out, out, M, D_MODEL, D_MODEL, 0);
}

// round 10
// speedup vs baseline: 2.2382x; 2.2382x over previous
#include <cuda_runtime.h>
#include <cuda_fp16.h>
#include <cstdint>
#include <cstddef>

#define D_MODEL 1024
#define N_HEADS 16
#define HEAD_DIM 64
#define BATCH 4
#define SEQ 2048
#define QKV_STRIDE (3 * D_MODEL)

// ------------------------------ scratch (fp16) -----------------------------
__device__ __half g_x16[(size_t)BATCH * SEQ * D_MODEL];
__device__ __half g_qkv16[(size_t)BATCH * SEQ * QKV_STRIDE];   // q cols pre-scaled 0.125
__device__ __half g_attn16[(size_t)BATCH * SEQ * D_MODEL];
__device__ __half g_wqkvT16[(size_t)3 * D_MODEL * D_MODEL];    // [3072][1024] k-major
__device__ __half g_woT16[(size_t)D_MODEL * D_MODEL];          // [1024][1024] k-major

// ------------------------------ helpers ------------------------------------
__device__ __forceinline__ uint32_t smem_u32(const void* p) {
    uint32_t a;
    asm("{ .reg .u64 t; cvta.to.shared.u64 t, %1; cvt.u32.u64 %0, t; }" : "=r"(a) : "l"(p));
    return a;
}
__device__ __forceinline__ void cp16(uint32_t dst, const void* src) {
    asm volatile("cp.async.ca.shared.global [%0], [%1], 16;" :: "r"(dst), "l"(src));
}
#define CP_COMMIT() asm volatile("cp.async.commit_group;" ::: "memory")
#define CP_WAIT0()  asm volatile("cp.async.wait_group 0;" ::: "memory")
#define CP_WAIT1()  asm volatile("cp.async.wait_group 1;" ::: "memory")

__device__ __forceinline__ void ldsm4(uint32_t* r, uint32_t addr) {
    asm volatile("ldmatrix.sync.aligned.m8n8.x4.shared.b16 {%0,%1,%2,%3}, [%4];"
        : "=r"(r[0]), "=r"(r[1]), "=r"(r[2]), "=r"(r[3]) : "r"(addr));
}
__device__ __forceinline__ void ldsm4t(uint32_t* r, uint32_t addr) {
    asm volatile("ldmatrix.sync.aligned.m8n8.x4.trans.shared.b16 {%0,%1,%2,%3}, [%4];"
        : "=r"(r[0]), "=r"(r[1]), "=r"(r[2]), "=r"(r[3]) : "r"(addr));
}

// D(f32) += A(f16) * B(f16) ; m16n8k16
__device__ __forceinline__ void mma16(float* c, const uint32_t* a, const uint32_t* b) {
    asm volatile(
        "mma.sync.aligned.m16n8k16.row.col.f32.f16.f16.f32 "
        "{%0,%1,%2,%3}, {%4,%5,%6,%7}, {%8,%9}, {%0,%1,%2,%3};"
        : "+f"(c[0]), "+f"(c[1]), "+f"(c[2]), "+f"(c[3])
        : "r"(a[0]), "r"(a[1]), "r"(a[2]), "r"(a[3]), "r"(b[0]), "r"(b[1]));
}

// ------------------------------ init kernels -------------------------------
__global__ void convert_x(const float* __restrict__ in, __half* __restrict__ out) {
    size_t i = ((size_t)blockIdx.x * blockDim.x + threadIdx.x) * 4;
    float4 v = *(const float4*)(in + i);
    *(__half2*)(out + i)     = __floats2half2_rn(v.x, v.y);
    *(__half2*)(out + i + 2) = __floats2half2_rn(v.z, v.w);
}

// out[C][R] = half(in[R][C])
__global__ void transpose_w(const float* __restrict__ in, __half* __restrict__ out,
                            int R, int C) {
    __shared__ float t[32][33];
    int c0 = blockIdx.x * 32, r0 = blockIdx.y * 32;
    #pragma unroll
    for (int j = 0; j < 4; j++) {
        int r = threadIdx.y + j * 8;
        t[r][threadIdx.x] = in[(size_t)(r0 + r) * C + c0 + threadIdx.x];
    }
    __syncthreads();
    #pragma unroll
    for (int j = 0; j < 4; j++) {
        int c = threadIdx.y + j * 8;
        out[(size_t)(c0 + c) * R + r0 + threadIdx.x] = __float2half_rn(t[threadIdx.x][c]);
    }
}

// ------------------------------ fp16 GEMM ----------------------------------
// C[M,N] = A[M,K] @ BT[N,K]^T + bias[N]. fp16 operands, fp32 accum.
// 128x128 CTA, BK=32, 3-stage cp.async, 256 thr / 8 warps, warp m32n64.
#define GS_STR 40   // halves per row (80B; 80 mod 128 = odd*16 -> ldsm conflict-free)
#define G_STAGES 3
#define G_SMEM (G_STAGES * 2 * 128 * GS_STR * 2)

template<bool ROUND>
__global__ void __launch_bounds__(256, 2) gemm_mma(
    const __half* __restrict__ A, const __half* __restrict__ BT,
    const float* __restrict__ bias, void* __restrict__ Cv,
    int M, int N, int K, int qcols)
{
    extern __shared__ __half smh[];
    __half* As = smh;                          // [3][128][GS_STR]
    __half* Bs = smh + G_STAGES * 128 * GS_STR;

    const int tid = threadIdx.x;
    const int lane = tid & 31, warp = tid >> 5;
    const int g = lane >> 2, q = lane & 3;
    const int wm = (warp >> 1) * 32, wn = (warp & 1) * 64;
    const int m0 = blockIdx.y * 128, n0 = blockIdx.x * 128;

    // loaders: 2 threads/row, each 2 x cp16 (16 halves)
    const int lrow = tid >> 1, lch = (tid & 1) * 16;  // half offset
    const __half* Ag = A + (size_t)(m0 + lrow) * K + lch;
    const __half* Bg = BT + (size_t)(n0 + lrow) * K + lch;
    const uint32_t asU = smem_u32(As), bsU = smem_u32(Bs);
    const uint32_t AsA = asU + (lrow * GS_STR + lch) * 2;
    const uint32_t BsA = bsU + (lrow * GS_STR + lch) * 2;

    // ldmatrix lane source offsets
    const int a_r = (lane & 7) + ((lane >> 3) & 1) * 8;
    const int a_h = (lane >> 4) * 8;              // k-half offset (chunk)
    const int b_n = (lane & 7) + ((lane >> 4) & 1) * 8;
    const int b_h = ((lane >> 3) & 1) * 8;
    const uint32_t aoff = ((wm + a_r) * GS_STR + a_h) * 2;
    const uint32_t boff = ((wn + b_n) * GS_STR + b_h) * 2;

    float acc[2][8][4];
    #pragma unroll
    for (int i = 0; i < 2; i++)
        #pragma unroll
        for (int j = 0; j < 8; j++)
            #pragma unroll
            for (int t = 0; t < 4; t++) acc[i][j][t] = 0.0f;

    const int nk = K >> 5;   // BK = 32 halves

    // prefetch stages 0,1
    #pragma unroll
    for (int s = 0; s < 2; s++) {
        uint32_t ad = AsA + s * 128 * GS_STR * 2;
        uint32_t bd = BsA + s * 128 * GS_STR * 2;
        cp16(ad, Ag + s * 32); cp16(ad + 16, Ag + s * 32 + 8);
        cp16(bd, Bg + s * 32); cp16(bd + 16, Bg + s * 32 + 8);
        CP_COMMIT();
    }

    for (int kt = 0; kt < nk; kt++) {
        CP_WAIT1();
        __syncthreads();
        if (kt + 2 < nk) {
            int s = (kt + 2) % G_STAGES;
            uint32_t ad = AsA + s * 128 * GS_STR * 2;
            uint32_t bd = BsA + s * 128 * GS_STR * 2;
            cp16(ad, Ag + (kt + 2) * 32); cp16(ad + 16, Ag + (kt + 2) * 32 + 8);
            cp16(bd, Bg + (kt + 2) * 32); cp16(bd + 16, Bg + (kt + 2) * 32 + 8);
        }
        CP_COMMIT();   // commit every iter (possibly empty) to keep group count in sync

        const int buf = kt % G_STAGES;
        const uint32_t aB = asU + buf * 128 * GS_STR * 2 + aoff;
        const uint32_t bB = bsU + buf * 128 * GS_STR * 2 + boff;
        #pragma unroll
        for (int kk = 0; kk < 32; kk += 16) {
            uint32_t af[2][4], bf[4][4];
            #pragma unroll
            for (int i = 0; i < 2; i++)
                ldsm4(af[i], aB + kk * 2 + i * 16 * GS_STR * 2);
            #pragma unroll
            for (int jp = 0; jp < 4; jp++)
                ldsm4(bf[jp], bB + kk * 2 + jp * 16 * GS_STR * 2);
            #pragma unroll
            for (int i = 0; i < 2; i++)
                #pragma unroll
                for (int jp = 0; jp < 4; jp++) {
                    mma16(acc[i][2 * jp],     af[i], &bf[jp][0]);
                    mma16(acc[i][2 * jp + 1], af[i], &bf[jp][2]);
                }
        }
    }

    // epilogue: acc + bias; ROUND -> fp16 C (q cols scaled 0.125), else fp32 C
    #pragma unroll
    for (int i = 0; i < 2; i++) {
        int row = m0 + wm + i * 16 + g;
        #pragma unroll
        for (int j = 0; j < 8; j++) {
            int col = n0 + wn + (j >> 1) * 16 + (j & 1) * 8 + 2 * q;
            float b0 = __ldg(&bias[col]), b1 = __ldg(&bias[col + 1]);
            float v0 = acc[i][j][0] + b0, v1 = acc[i][j][1] + b1;
            float v2 = acc[i][j][2] + b0, v3 = acc[i][j][3] + b1;
            if (ROUND) {
                __half* Ch = (__half*)Cv;
                float sc = (col < qcols) ? 0.125f : 1.0f;
                *(__half2*)(Ch + (size_t)row * N + col) =
                    __floats2half2_rn(v0 * sc, v1 * sc);
                *(__half2*)(Ch + (size_t)(row + 8) * N + col) =
                    __floats2half2_rn(v2 * sc, v3 * sc);
            } else {
                float* Cf = (float*)Cv;
                *(float2*)(Cf + (size_t)row * N + col) = make_float2(v0, v1);
                *(float2*)(Cf + (size_t)(row + 8) * N + col) = make_float2(v2, v3);
            }
        }
    }
}

// ------------------------------ attention ----------------------------------
// Flash, BQ=128, BKV=64, 8 warps; warp w owns q-rows [w*16, w*16+16).
// fp16 tiles; V fragments via ldmatrix.trans; P staged fp16 (warp-private rows).
#define AQ_STR 72   // halves (144B rows; 144 mod 128 = 16 -> conflict-free)
#define A_SMEM ((128 * AQ_STR + 64 * AQ_STR + 64 * AQ_STR + 128 * AQ_STR) * 2)

__global__ void __launch_bounds__(256, 2) attn_mma()
{
    extern __shared__ __half smh[];
    __half* Qs = smh;                    // [128][72] (pre-scaled)
    __half* Ks = Qs + 128 * AQ_STR;      // [64][72]
    __half* Vs = Ks + 64 * AQ_STR;       // [64][72]
    __half* Ps = Vs + 64 * AQ_STR;       // [128][72]

    const int tid = threadIdx.x;
    const int lane = tid & 31, warp = tid >> 5;
    const int g = lane >> 2, q = lane & 3;
    const int qt = gridDim.x - 1 - blockIdx.x;   // heaviest tiles first
    const int q0 = qt * 128;
    const int h = blockIdx.y, b = blockIdx.z;

    const __half* base = g_qkv16 + (size_t)b * SEQ * QKV_STRIDE + h * HEAD_DIM;
    const uint32_t qsU = smem_u32(Qs), ksU = smem_u32(Ks);
    const uint32_t vsU = smem_u32(Vs), psU = smem_u32(Ps);

    // ldmatrix lane source offsets
    const int a_r = (lane & 7) + ((lane >> 3) & 1) * 8;
    const int a_h = (lane >> 4) * 8;
    const int b_n = (lane & 7) + ((lane >> 4) & 1) * 8;
    const int b_h = ((lane >> 3) & 1) * 8;
    const int v_r = (lane & 7) + ((lane >> 3) & 1) * 8;   // kv row (trans)
    const int v_h = (lane >> 4) * 8;                      // d chunk
    const uint32_t aoffQ = ((warp * 16 + a_r) * AQ_STR + a_h) * 2;
    const uint32_t boffK = (b_n * AQ_STR + b_h) * 2;

    // load Q tile: 128 rows x 64 halves = 1024 cp16 / 256 thr = 4 each
    #pragma unroll
    for (int jj = 0; jj < 4; jj++) {
        int idx = tid + 256 * jj;
        int row = idx >> 3, ch = (idx & 7) * 8;
        cp16(qsU + (row * AQ_STR + ch) * 2, base + (size_t)(q0 + row) * QKV_STRIDE + ch);
    }
    CP_COMMIT();

    float m0r[2] = {-1e30f, -1e30f};
    float lr[2] = {0.0f, 0.0f};
    float O[8][4];
    #pragma unroll
    for (int j = 0; j < 8; j++)
        #pragma unroll
        for (int t = 0; t < 4; t++) O[j][t] = 0.0f;

    const int ra = q0 + warp * 16 + g;
    const int rb = ra + 8;
    const int nkv = 2 * (qt + 1);

    for (int kv = 0; kv < nkv; kv++) {
        const int kv0 = kv * 64;
        __syncthreads();
        // load K,V: 64 rows x 64 halves = 512 cp16 each -> 2+2 per thread
        #pragma unroll
        for (int jj = 0; jj < 2; jj++) {
            int idx = tid + 256 * jj;
            int row = idx >> 3, ch = (idx & 7) * 8;
            const __half* src = base + (size_t)(kv0 + row) * QKV_STRIDE + ch;
            cp16(ksU + (row * AQ_STR + ch) * 2, src + D_MODEL);
            cp16(vsU + (row * AQ_STR + ch) * 2, src + 2 * D_MODEL);
        }
        CP_COMMIT();
        CP_WAIT0();
        __syncthreads();

        // S = Q K^T  (m16 x n64 per warp, k=64)
        float sacc[8][4];
        #pragma unroll
        for (int j = 0; j < 8; j++)
            #pragma unroll
            for (int t = 0; t < 4; t++) sacc[j][t] = 0.0f;
        #pragma unroll
        for (int kk = 0; kk < 64; kk += 16) {
            uint32_t af[4], bf[4][4];
            ldsm4(af, qsU + aoffQ + kk * 2);
            #pragma unroll
            for (int jp = 0; jp < 4; jp++)
                ldsm4(bf[jp], ksU + boffK + kk * 2 + jp * 16 * AQ_STR * 2);
            #pragma unroll
            for (int jp = 0; jp < 4; jp++) {
                mma16(sacc[2 * jp],     af, &bf[jp][0]);
                mma16(sacc[2 * jp + 1], af, &bf[jp][2]);
            }
        }

        // causal mask (diagonal reachable only in last two kv tiles)
        if (kv >= nkv - 2) {
            #pragma unroll
            for (int j = 0; j < 8; j++) {
                int c0 = kv0 + (j >> 1) * 16 + (j & 1) * 8 + 2 * q;
                if (c0 > ra)     sacc[j][0] = -1e30f;
                if (c0 + 1 > ra) sacc[j][1] = -1e30f;
                if (c0 > rb)     sacc[j][2] = -1e30f;
                if (c0 + 1 > rb) sacc[j][3] = -1e30f;
            }
        }

        // row max
        float mxa = -1e30f, mxb = -1e30f;
        #pragma unroll
        for (int j = 0; j < 8; j++) {
            mxa = fmaxf(mxa, fmaxf(sacc[j][0], sacc[j][1]));
            mxb = fmaxf(mxb, fmaxf(sacc[j][2], sacc[j][3]));
        }
        mxa = fmaxf(mxa, __shfl_xor_sync(0xffffffff, mxa, 1));
        mxa = fmaxf(mxa, __shfl_xor_sync(0xffffffff, mxa, 2));
        mxb = fmaxf(mxb, __shfl_xor_sync(0xffffffff, mxb, 1));
        mxb = fmaxf(mxb, __shfl_xor_sync(0xffffffff, mxb, 2));

        float mna = fmaxf(m0r[0], mxa), mnb = fmaxf(m0r[1], mxb);
        float aa = __expf(m0r[0] - mna), ab = __expf(m0r[1] - mnb);
        m0r[0] = mna; m0r[1] = mnb;

        // exp + P store (fp16 pairs) + row sums
        float sa = 0.0f, sb = 0.0f;
        __half* prow_a = Ps + (warp * 16 + g) * AQ_STR;
        __half* prow_b = prow_a + 8 * AQ_STR;
        #pragma unroll
        for (int j = 0; j < 8; j++) {
            float p0 = __expf(sacc[j][0] - mna);
            float p1 = __expf(sacc[j][1] - mna);
            float p2 = __expf(sacc[j][2] - mnb);
            float p3 = __expf(sacc[j][3] - mnb);
            sa += p0 + p1; sb += p2 + p3;
            int c = (j >> 1) * 16 + (j & 1) * 8 + 2 * q;
            *(__half2*)(prow_a + c) = __floats2half2_rn(p0, p1);
            *(__half2*)(prow_b + c) = __floats2half2_rn(p2, p3);
        }
        sa += __shfl_xor_sync(0xffffffff, sa, 1);
        sa += __shfl_xor_sync(0xffffffff, sa, 2);
        sb += __shfl_xor_sync(0xffffffff, sb, 1);
        sb += __shfl_xor_sync(0xffffffff, sb, 2);
        lr[0] = lr[0] * aa + sa;
        lr[1] = lr[1] * ab + sb;
        #pragma unroll
        for (int j = 0; j < 8; j++) {
            O[j][0] *= aa; O[j][1] *= aa;
            O[j][2] *= ab; O[j][3] *= ab;
        }
        __syncwarp();   // order Ps stores -> ldmatrix (warp-private rows)

        // O += P @ V  (m16 x n64, k=64); V via ldmatrix.trans
        #pragma unroll
        for (int kk = 0; kk < 64; kk += 16) {
            uint32_t af[4], bf[4][4];
            ldsm4(af, psU + aoffQ + kk * 2);
            #pragma unroll
            for (int jp = 0; jp < 4; jp++)
                ldsm4t(bf[jp], vsU + ((kk + v_r) * AQ_STR + jp * 16 + v_h) * 2);
            #pragma unroll
            for (int jp = 0; jp < 4; jp++) {
                mma16(O[2 * jp],     af, &bf[jp][0]);
                mma16(O[2 * jp + 1], af, &bf[jp][2]);
            }
        }
    }

    // epilogue: normalize, write fp16 [b,t,h*64+d]
    float inva = 1.0f / lr[0], invb = 1.0f / lr[1];
    __half* outa = g_attn16 + ((size_t)b * SEQ + ra) * D_MODEL + h * HEAD_DIM;
    __half* outb = g_attn16 + ((size_t)b * SEQ + rb) * D_MODEL + h * HEAD_DIM;
    #pragma unroll
    for (int j = 0; j < 8; j++) {
        int c = (j >> 1) * 16 + (j & 1) * 8 + 2 * q;
        *(__half2*)(outa + c) = __floats2half2_rn(O[j][0] * inva, O[j][1] * inva);
        *(__half2*)(outb + c) = __floats2half2_rn(O[j][2] * invb, O[j][3] * invb);
    }
}

// ---------------------------------------------------------------------------
extern "C" void kernel_launch(void* const* d_in, const int* in_sizes, int n_in,
                              void* d_out, int out_size)
{
    (void)in_sizes; (void)n_in; (void)out_size;
    const float* x     = (const float*)d_in[0];
    const float* w_qkv = (const float*)d_in[1];
    const float* b_qkv = (const float*)d_in[2];
    const float* w_out = (const float*)d_in[3];
    const float* b_out = (const float*)d_in[4];
    float* out = (float*)d_out;

    __half *x16, *qkv16, *attn16, *wqkvT16, *woT16;
    cudaGetSymbolAddress((void**)&x16, g_x16);
    cudaGetSymbolAddress((void**)&qkv16, g_qkv16);
    cudaGetSymbolAddress((void**)&attn16, g_attn16);
    cudaGetSymbolAddress((void**)&wqkvT16, g_wqkvT16);
    cudaGetSymbolAddress((void**)&woT16, g_woT16);

    cudaFuncSetAttribute(gemm_mma<true>,  cudaFuncAttributeMaxDynamicSharedMemorySize, G_SMEM);
    cudaFuncSetAttribute(gemm_mma<false>, cudaFuncAttributeMaxDynamicSharedMemorySize, G_SMEM);
    cudaFuncSetAttribute(attn_mma, cudaFuncAttributeMaxDynamicSharedMemorySize, A_SMEM);

    const int M = BATCH * SEQ;  // 8192

    // init: fp16 conversions
    convert_x<<<(M * D_MODEL) / (256 * 4), 256>>>(x, x16);
    transpose_w<<<dim3(3 * D_MODEL / 32, D_MODEL / 32), dim3(32, 8)>>>(w_qkv, wqkvT16, D_MODEL, 3 * D_MODEL);
    transpose_w<<<dim3(D_MODEL / 32, D_MODEL / 32), dim3(32, 8)>>>(w_out, woT16, D_MODEL, D_MODEL);

    // 1) QKV projection (fp16 out, q cols pre-scaled by 0.125)
    gemm_mma<true><<<dim3(3 * D_MODEL / 128, M / 128), 256, G_SMEM>>>(
        x16, wqkvT16, b_qkv, qkv16, M, 3 * D_MODEL, D_MODEL, D_MODEL);

    // 2) causal flash attention (fp16 in/out)
    attn_mma<<<dim3(SEQ / 128, N_HEADS, BATCH), 256, A_SMEM>>>();

    // 3) output projection (fp32 out)
    gemm_mma<false><<<dim3(D_MODEL / 128, M / 128), 256, G_SMEM>>>(
        attn16, woT16, b_out, out, M, D_MODEL, D_MODEL, 0);
}

// round 12
// speedup vs baseline: 2.3258x; 1.0391x over previous
#include <cuda_runtime.h>
#include <cuda_fp16.h>
#include <cstdint>
#include <cstddef>

#define D_MODEL 1024
#define N_HEADS 16
#define HEAD_DIM 64
#define BATCH 4
#define SEQ 2048
#define QKV_STRIDE (3 * D_MODEL)

// ------------------------------ scratch (fp16) -----------------------------
__device__ __half g_x16[(size_t)BATCH * SEQ * D_MODEL];
__device__ __half g_qkv16[(size_t)BATCH * SEQ * QKV_STRIDE];   // q cols pre-scaled 0.125*log2e
__device__ __half g_attn16[(size_t)BATCH * SEQ * D_MODEL];
__device__ __half g_wqkvT16[(size_t)3 * D_MODEL * D_MODEL];    // [3072][1024] k-major
__device__ __half g_woT16[(size_t)D_MODEL * D_MODEL];          // [1024][1024] k-major

// ------------------------------ helpers ------------------------------------
__device__ __forceinline__ uint32_t smem_u32(const void* p) {
    uint32_t a;
    asm("{ .reg .u64 t; cvta.to.shared.u64 t, %1; cvt.u32.u64 %0, t; }" : "=r"(a) : "l"(p));
    return a;
}
__device__ __forceinline__ uint32_t h2u(__half2 h) {
    return *reinterpret_cast<uint32_t*>(&h);
}
__device__ __forceinline__ void cp16(uint32_t dst, const void* src) {
    asm volatile("cp.async.ca.shared.global [%0], [%1], 16;" :: "r"(dst), "l"(src));
}
#define CP_COMMIT() asm volatile("cp.async.commit_group;" ::: "memory")
#define CP_WAIT0()  asm volatile("cp.async.wait_group 0;" ::: "memory")
#define CP_WAIT1()  asm volatile("cp.async.wait_group 1;" ::: "memory")

__device__ __forceinline__ void ldsm4(uint32_t* r, uint32_t addr) {
    asm volatile("ldmatrix.sync.aligned.m8n8.x4.shared.b16 {%0,%1,%2,%3}, [%4];"
        : "=r"(r[0]), "=r"(r[1]), "=r"(r[2]), "=r"(r[3]) : "r"(addr));
}
__device__ __forceinline__ void ldsm4t(uint32_t* r, uint32_t addr) {
    asm volatile("ldmatrix.sync.aligned.m8n8.x4.trans.shared.b16 {%0,%1,%2,%3}, [%4];"
        : "=r"(r[0]), "=r"(r[1]), "=r"(r[2]), "=r"(r[3]) : "r"(addr));
}

// D(f32) += A(f16) * B(f16) ; m16n8k16
__device__ __forceinline__ void mma16(float* c, const uint32_t* a, const uint32_t* b) {
    asm volatile(
        "mma.sync.aligned.m16n8k16.row.col.f32.f16.f16.f32 "
        "{%0,%1,%2,%3}, {%4,%5,%6,%7}, {%8,%9}, {%0,%1,%2,%3};"
        : "+f"(c[0]), "+f"(c[1]), "+f"(c[2]), "+f"(c[3])
        : "r"(a[0]), "r"(a[1]), "r"(a[2]), "r"(a[3]), "r"(b[0]), "r"(b[1]));
}

// ------------------------------ init kernels -------------------------------
__global__ void convert_x(const float* __restrict__ in, __half* __restrict__ out) {
    size_t i = ((size_t)blockIdx.x * blockDim.x + threadIdx.x) * 4;
    float4 v = *(const float4*)(in + i);
    *(__half2*)(out + i)     = __floats2half2_rn(v.x, v.y);
    *(__half2*)(out + i + 2) = __floats2half2_rn(v.z, v.w);
}

// out[C][R] = half(in[R][C])
__global__ void transpose_w(const float* __restrict__ in, __half* __restrict__ out,
                            int R, int C) {
    __shared__ float t[32][33];
    int c0 = blockIdx.x * 32, r0 = blockIdx.y * 32;
    #pragma unroll
    for (int j = 0; j < 4; j++) {
        int r = threadIdx.y + j * 8;
        t[r][threadIdx.x] = in[(size_t)(r0 + r) * C + c0 + threadIdx.x];
    }
    __syncthreads();
    #pragma unroll
    for (int j = 0; j < 4; j++) {
        int c = threadIdx.y + j * 8;
        out[(size_t)(c0 + c) * R + r0 + threadIdx.x] = __float2half_rn(t[threadIdx.x][c]);
    }
}

// ------------------------------ fp16 GEMM ----------------------------------
// C[M,N] = A[M,K] @ BT[N,K]^T + bias[N]. fp16 operands, fp32 accum.
// 128x128 CTA, BK=32, 3-stage cp.async, 256 thr / 8 warps, warp m32n64.
#define GS_STR 40
#define G_STAGES 3
#define G_SMEM (G_STAGES * 2 * 128 * GS_STR * 2)
#define QSCALE (0.125f * 1.44269504088896f)   // fold softmax scale + log2e into Q

template<bool ROUND>
__global__ void __launch_bounds__(256, 2) gemm_mma(
    const __half* __restrict__ A, const __half* __restrict__ BT,
    const float* __restrict__ bias, void* __restrict__ Cv,
    int M, int N, int K, int qcols)
{
    extern __shared__ __half smh[];
    __half* As = smh;                          // [3][128][GS_STR]
    __half* Bs = smh + G_STAGES * 128 * GS_STR;

    const int tid = threadIdx.x;
    const int lane = tid & 31, warp = tid >> 5;
    const int g = lane >> 2, q = lane & 3;
    const int wm = (warp >> 1) * 32, wn = (warp & 1) * 64;
    const int m0 = blockIdx.y * 128, n0 = blockIdx.x * 128;

    const int lrow = tid >> 1, lch = (tid & 1) * 16;
    const __half* Ag = A + (size_t)(m0 + lrow) * K + lch;
    const __half* Bg = BT + (size_t)(n0 + lrow) * K + lch;
    const uint32_t asU = smem_u32(As), bsU = smem_u32(Bs);
    const uint32_t AsA = asU + (lrow * GS_STR + lch) * 2;
    const uint32_t BsA = bsU + (lrow * GS_STR + lch) * 2;

    const int a_r = (lane & 7) + ((lane >> 3) & 1) * 8;
    const int a_h = (lane >> 4) * 8;
    const int b_n = (lane & 7) + ((lane >> 4) & 1) * 8;
    const int b_h = ((lane >> 3) & 1) * 8;
    const uint32_t aoff = ((wm + a_r) * GS_STR + a_h) * 2;
    const uint32_t boff = ((wn + b_n) * GS_STR + b_h) * 2;

    float acc[2][8][4];
    #pragma unroll
    for (int i = 0; i < 2; i++)
        #pragma unroll
        for (int j = 0; j < 8; j++)
            #pragma unroll
            for (int t = 0; t < 4; t++) acc[i][j][t] = 0.0f;

    const int nk = K >> 5;

    #pragma unroll
    for (int s = 0; s < 2; s++) {
        uint32_t ad = AsA + s * 128 * GS_STR * 2;
        uint32_t bd = BsA + s * 128 * GS_STR * 2;
        cp16(ad, Ag + s * 32); cp16(ad + 16, Ag + s * 32 + 8);
        cp16(bd, Bg + s * 32); cp16(bd + 16, Bg + s * 32 + 8);
        CP_COMMIT();
    }

    for (int kt = 0; kt < nk; kt++) {
        CP_WAIT1();
        __syncthreads();
        if (kt + 2 < nk) {
            int s = (kt + 2) % G_STAGES;
            uint32_t ad = AsA + s * 128 * GS_STR * 2;
            uint32_t bd = BsA + s * 128 * GS_STR * 2;
            cp16(ad, Ag + (kt + 2) * 32); cp16(ad + 16, Ag + (kt + 2) * 32 + 8);
            cp16(bd, Bg + (kt + 2) * 32); cp16(bd + 16, Bg + (kt + 2) * 32 + 8);
        }
        CP_COMMIT();

        const int buf = kt % G_STAGES;
        const uint32_t aB = asU + buf * 128 * GS_STR * 2 + aoff;
        const uint32_t bB = bsU + buf * 128 * GS_STR * 2 + boff;
        #pragma unroll
        for (int kk = 0; kk < 32; kk += 16) {
            uint32_t af[2][4], bf[4][4];
            #pragma unroll
            for (int i = 0; i < 2; i++)
                ldsm4(af[i], aB + kk * 2 + i * 16 * GS_STR * 2);
            #pragma unroll
            for (int jp = 0; jp < 4; jp++)
                ldsm4(bf[jp], bB + kk * 2 + jp * 16 * GS_STR * 2);
            #pragma unroll
            for (int i = 0; i < 2; i++)
                #pragma unroll
                for (int jp = 0; jp < 4; jp++) {
                    mma16(acc[i][2 * jp],     af[i], &bf[jp][0]);
                    mma16(acc[i][2 * jp + 1], af[i], &bf[jp][2]);
                }
        }
    }

    #pragma unroll
    for (int i = 0; i < 2; i++) {
        int row = m0 + wm + i * 16 + g;
        #pragma unroll
        for (int j = 0; j < 8; j++) {
            int col = n0 + wn + (j >> 1) * 16 + (j & 1) * 8 + 2 * q;
            float b0 = __ldg(&bias[col]), b1 = __ldg(&bias[col + 1]);
            float v0 = acc[i][j][0] + b0, v1 = acc[i][j][1] + b1;
            float v2 = acc[i][j][2] + b0, v3 = acc[i][j][3] + b1;
            if (ROUND) {
                __half* Ch = (__half*)Cv;
                float sc = (col < qcols) ? QSCALE : 1.0f;
                *(__half2*)(Ch + (size_t)row * N + col) =
                    __floats2half2_rn(v0 * sc, v1 * sc);
                *(__half2*)(Ch + (size_t)(row + 8) * N + col) =
                    __floats2half2_rn(v2 * sc, v3 * sc);
            } else {
                float* Cf = (float*)Cv;
                *(float2*)(Cf + (size_t)row * N + col) = make_float2(v0, v1);
                *(float2*)(Cf + (size_t)(row + 8) * N + col) = make_float2(v2, v3);
            }
        }
    }
}

// ------------------------------ attention ----------------------------------
// Flash, BQ=128, BKV=64, 8 warps; warp w owns q-rows [w*16, w*16+16).
// P built directly from S accumulator registers (C-frag == A-frag layout).
// K/V double-buffered cp.async; one __syncthreads per kv iteration.
#define AQ_STR 72          // halves per row (144B)
#define KV_TILE (64 * AQ_STR)
#define A_SMEM ((128 * AQ_STR + 4 * KV_TILE) * 2)

__global__ void __launch_bounds__(256, 2) attn_mma()
{
    extern __shared__ __half smh[];
    __half* Qs = smh;                 // [128][72] (pre-scaled by 0.125*log2e)
    // buffers: [b][ K:64x72 | V:64x72 ]
    const uint32_t qsU = smem_u32(Qs);
    const uint32_t kvU = qsU + 128 * AQ_STR * 2;

    const int tid = threadIdx.x;
    const int lane = tid & 31, warp = tid >> 5;
    const int g = lane >> 2, q = lane & 3;
    const int qt = gridDim.x - 1 - blockIdx.x;   // heaviest tiles first
    const int q0 = qt * 128;
    const int h = blockIdx.y, b = blockIdx.z;

    const __half* base = g_qkv16 + (size_t)b * SEQ * QKV_STRIDE + h * HEAD_DIM;

    // ldmatrix lane source offsets
    const int a_r = (lane & 7) + ((lane >> 3) & 1) * 8;
    const int a_h = (lane >> 4) * 8;
    const int b_n = (lane & 7) + ((lane >> 4) & 1) * 8;
    const int b_h = ((lane >> 3) & 1) * 8;
    const int v_r = (lane & 7) + ((lane >> 3) & 1) * 8;
    const int v_h = (lane >> 4) * 8;
    const uint32_t aoffQ = ((warp * 16 + a_r) * AQ_STR + a_h) * 2;
    const uint32_t boffK = (b_n * AQ_STR + b_h) * 2;

    // loader mapping for K/V tiles: 64 rows x 64 halves, 2 cp16/thread each
    const int krow = tid >> 2, kch = (tid & 3) * 16;    // 256 thr cover 64x64
    const __half* kvsrc = base + (size_t)krow * QKV_STRIDE + kch;

    // prologue: Q tile + kv0 K/V, single commit group
    #pragma unroll
    for (int jj = 0; jj < 4; jj++) {
        int idx = tid + 256 * jj;
        int row = idx >> 3, ch = (idx & 7) * 8;
        cp16(qsU + (row * AQ_STR + ch) * 2, base + (size_t)(q0 + row) * QKV_STRIDE + ch);
    }
    {
        uint32_t kd = kvU + (krow * AQ_STR + kch) * 2;
        cp16(kd, kvsrc + D_MODEL);     cp16(kd + 16, kvsrc + D_MODEL + 8);
        uint32_t vd = kd + KV_TILE * 2;
        cp16(vd, kvsrc + 2 * D_MODEL); cp16(vd + 16, kvsrc + 2 * D_MODEL + 8);
    }
    CP_COMMIT();

    float m0r[2] = {-1e30f, -1e30f};
    float lr[2] = {0.0f, 0.0f};
    float O[8][4];
    #pragma unroll
    for (int j = 0; j < 8; j++)
        #pragma unroll
        for (int t = 0; t < 4; t++) O[j][t] = 0.0f;

    const int ra = q0 + warp * 16 + g;
    const int rb = ra + 8;
    const int nkv = 2 * (qt + 1);

    for (int kv = 0; kv < nkv; kv++) {
        const int kv0 = kv * 64;
        CP_WAIT0();
        __syncthreads();
        // prefetch next kv tile into the other buffer (overlaps compute below)
        if (kv + 1 < nkv) {
            uint32_t bufn = ((kv + 1) & 1) * 2 * KV_TILE * 2;
            const __half* src = kvsrc + (size_t)(kv0 + 64) * QKV_STRIDE;
            uint32_t kd = kvU + bufn + (krow * AQ_STR + kch) * 2;
            cp16(kd, src + D_MODEL);     cp16(kd + 16, src + D_MODEL + 8);
            uint32_t vd = kd + KV_TILE * 2;
            cp16(vd, src + 2 * D_MODEL); cp16(vd + 16, src + 2 * D_MODEL + 8);
        }
        CP_COMMIT();

        const uint32_t kB = kvU + (kv & 1) * 2 * KV_TILE * 2;
        const uint32_t vB = kB + KV_TILE * 2;

        // S = Q K^T  (m16 x n64 per warp, k=64)
        float sacc[8][4];
        #pragma unroll
        for (int j = 0; j < 8; j++)
            #pragma unroll
            for (int t = 0; t < 4; t++) sacc[j][t] = 0.0f;
        #pragma unroll
        for (int kk = 0; kk < 64; kk += 16) {
            uint32_t af[4], bf[4][4];
            ldsm4(af, qsU + aoffQ + kk * 2);
            #pragma unroll
            for (int jp = 0; jp < 4; jp++)
                ldsm4(bf[jp], kB + boffK + kk * 2 + jp * 16 * AQ_STR * 2);
            #pragma unroll
            for (int jp = 0; jp < 4; jp++) {
                mma16(sacc[2 * jp],     af, &bf[jp][0]);
                mma16(sacc[2 * jp + 1], af, &bf[jp][2]);
            }
        }

        // causal mask (diagonal reachable only in last two kv tiles)
        if (kv >= nkv - 2) {
            #pragma unroll
            for (int j = 0; j < 8; j++) {
                int c0 = kv0 + (j >> 1) * 16 + (j & 1) * 8 + 2 * q;
                if (c0 > ra)     sacc[j][0] = -1e30f;
                if (c0 + 1 > ra) sacc[j][1] = -1e30f;
                if (c0 > rb)     sacc[j][2] = -1e30f;
                if (c0 + 1 > rb) sacc[j][3] = -1e30f;
            }
        }

        // row max (log2 domain)
        float mxa = -1e30f, mxb = -1e30f;
        #pragma unroll
        for (int j = 0; j < 8; j++) {
            mxa = fmaxf(mxa, fmaxf(sacc[j][0], sacc[j][1]));
            mxb = fmaxf(mxb, fmaxf(sacc[j][2], sacc[j][3]));
        }
        mxa = fmaxf(mxa, __shfl_xor_sync(0xffffffff, mxa, 1));
        mxa = fmaxf(mxa, __shfl_xor_sync(0xffffffff, mxa, 2));
        mxb = fmaxf(mxb, __shfl_xor_sync(0xffffffff, mxb, 1));
        mxb = fmaxf(mxb, __shfl_xor_sync(0xffffffff, mxb, 2));

        float mna = fmaxf(m0r[0], mxa), mnb = fmaxf(m0r[1], mxb);
        float aa = exp2f(m0r[0] - mna), ab = exp2f(m0r[1] - mnb);
        m0r[0] = mna; m0r[1] = mnb;

        // exp2 + pack P into A-fragments directly (C-frag layout == A-frag layout)
        float sa = 0.0f, sb = 0.0f;
        uint32_t pl[8], ph[8];
        #pragma unroll
        for (int j = 0; j < 8; j++) {
            float p0 = exp2f(sacc[j][0] - mna);
            float p1 = exp2f(sacc[j][1] - mna);
            float p2 = exp2f(sacc[j][2] - mnb);
            float p3 = exp2f(sacc[j][3] - mnb);
            sa += p0 + p1; sb += p2 + p3;
            pl[j] = h2u(__floats2half2_rn(p0, p1));   // rows g
            ph[j] = h2u(__floats2half2_rn(p2, p3));   // rows g+8
        }
        sa += __shfl_xor_sync(0xffffffff, sa, 1);
        sa += __shfl_xor_sync(0xffffffff, sa, 2);
        sb += __shfl_xor_sync(0xffffffff, sb, 1);
        sb += __shfl_xor_sync(0xffffffff, sb, 2);
        lr[0] = lr[0] * aa + sa;
        lr[1] = lr[1] * ab + sb;
        #pragma unroll
        for (int j = 0; j < 8; j++) {
            O[j][0] *= aa; O[j][1] *= aa;
            O[j][2] *= ab; O[j][3] *= ab;
        }

        // O += P @ V  (m16 x n64, k=64); P from registers, V via ldmatrix.trans
        #pragma unroll
        for (int t = 0; t < 4; t++) {          // k-chunk 16t..16t+16
            uint32_t af[4] = {pl[2 * t], ph[2 * t], pl[2 * t + 1], ph[2 * t + 1]};
            uint32_t bf[4][4];
            #pragma unroll
            for (int jp = 0; jp < 4; jp++)
                ldsm4t(bf[jp], vB + ((16 * t + v_r) * AQ_STR + jp * 16 + v_h) * 2);
            #pragma unroll
            for (int jp = 0; jp < 4; jp++) {
                mma16(O[2 * jp],     af, &bf[jp][0]);
                mma16(O[2 * jp + 1], af, &bf[jp][2]);
            }
        }
    }

    // epilogue: normalize, write fp16 [b,t,h*64+d]
    float inva = 1.0f / lr[0], invb = 1.0f / lr[1];
    __half* outa = g_attn16 + ((size_t)b * SEQ + ra) * D_MODEL + h * HEAD_DIM;
    __half* outb = g_attn16 + ((size_t)b * SEQ + rb) * D_MODEL + h * HEAD_DIM;
    #pragma unroll
    for (int j = 0; j < 8; j++) {
        int c = (j >> 1) * 16 + (j & 1) * 8 + 2 * q;
        *(__half2*)(outa + c) = __floats2half2_rn(O[j][0] * inva, O[j][1] * inva);
        *(__half2*)(outb + c) = __floats2half2_rn(O[j][2] * invb, O[j][3] * invb);
    }
}

// ---------------------------------------------------------------------------
extern "C" void kernel_launch(void* const* d_in, const int* in_sizes, int n_in,
                              void* d_out, int out_size)
{
    (void)in_sizes; (void)n_in; (void)out_size;
    const float* x     = (const float*)d_in[0];
    const float* w_qkv = (const float*)d_in[1];
    const float* b_qkv = (const float*)d_in[2];
    const float* w_out = (const float*)d_in[3];
    const float* b_out = (const float*)d_in[4];
    float* out = (float*)d_out;

    __half *x16, *qkv16, *attn16, *wqkvT16, *woT16;
    cudaGetSymbolAddress((void**)&x16, g_x16);
    cudaGetSymbolAddress((void**)&qkv16, g_qkv16);
    cudaGetSymbolAddress((void**)&attn16, g_attn16);
    cudaGetSymbolAddress((void**)&wqkvT16, g_wqkvT16);
    cudaGetSymbolAddress((void**)&woT16, g_woT16);

    cudaFuncSetAttribute(gemm_mma<true>,  cudaFuncAttributeMaxDynamicSharedMemorySize, G_SMEM);
    cudaFuncSetAttribute(gemm_mma<false>, cudaFuncAttributeMaxDynamicSharedMemorySize, G_SMEM);
    cudaFuncSetAttribute(attn_mma, cudaFuncAttributeMaxDynamicSharedMemorySize, A_SMEM);

    const int M = BATCH * SEQ;  // 8192

    convert_x<<<(M * D_MODEL) / (256 * 4), 256>>>(x, x16);
    transpose_w<<<dim3(3 * D_MODEL / 32, D_MODEL / 32), dim3(32, 8)>>>(w_qkv, wqkvT16, D_MODEL, 3 * D_MODEL);
    transpose_w<<<dim3(D_MODEL / 32, D_MODEL / 32), dim3(32, 8)>>>(w_out, woT16, D_MODEL, D_MODEL);

    // 1) QKV projection (fp16 out, q cols pre-scaled by 0.125*log2e)
    gemm_mma<true><<<dim3(3 * D_MODEL / 128, M / 128), 256, G_SMEM>>>(
        x16, wqkvT16, b_qkv, qkv16, M, 3 * D_MODEL, D_MODEL, D_MODEL);

    // 2) causal flash attention (fp16 in/out)
    attn_mma<<<dim3(SEQ / 128, N_HEADS, BATCH), 256, A_SMEM>>>();

    // 3) output projection (fp32 out)
    gemm_mma<false><<<dim3(D_MODEL / 128, M / 128), 256, G_SMEM>>>(
        attn16, woT16, b_out, out, M, D_MODEL, D_MODEL, 0);
}

// round 13
// speedup vs baseline: 2.4522x; 1.0543x over previous
#include <cuda_runtime.h>
#include <cuda_fp16.h>
#include <cstdint>
#include <cstddef>

#define D_MODEL 1024
#define N_HEADS 16
#define HEAD_DIM 64
#define BATCH 4
#define SEQ 2048
#define QKV_STRIDE (3 * D_MODEL)

// ------------------------------ scratch (fp16) -----------------------------
__device__ __half g_x16[(size_t)BATCH * SEQ * D_MODEL];
__device__ __half g_qkv16[(size_t)BATCH * SEQ * QKV_STRIDE];   // q cols pre-scaled 0.125*log2e
__device__ __half g_attn16[(size_t)BATCH * SEQ * D_MODEL];
__device__ __half g_wqkvT16[(size_t)3 * D_MODEL * D_MODEL];    // [3072][1024] k-major
__device__ __half g_woT16[(size_t)D_MODEL * D_MODEL];          // [1024][1024] k-major

// ------------------------------ helpers ------------------------------------
__device__ __forceinline__ uint32_t smem_u32(const void* p) {
    uint32_t a;
    asm("{ .reg .u64 t; cvta.to.shared.u64 t, %1; cvt.u32.u64 %0, t; }" : "=r"(a) : "l"(p));
    return a;
}
__device__ __forceinline__ uint32_t h2u(__half2 h) {
    return *reinterpret_cast<uint32_t*>(&h);
}
__device__ __forceinline__ uint32_t ex2_h2(uint32_t x) {
    uint32_t r; asm("ex2.approx.f16x2 %0, %1;" : "=r"(r) : "r"(x)); return r;
}
__device__ __forceinline__ void cp16(uint32_t dst, const void* src) {
    asm volatile("cp.async.ca.shared.global [%0], [%1], 16;" :: "r"(dst), "l"(src));
}
#define CP_COMMIT() asm volatile("cp.async.commit_group;" ::: "memory")
#define CP_WAIT0()  asm volatile("cp.async.wait_group 0;" ::: "memory")
#define CP_WAIT1()  asm volatile("cp.async.wait_group 1;" ::: "memory")

__device__ __forceinline__ void ldsm4(uint32_t* r, uint32_t addr) {
    asm volatile("ldmatrix.sync.aligned.m8n8.x4.shared.b16 {%0,%1,%2,%3}, [%4];"
        : "=r"(r[0]), "=r"(r[1]), "=r"(r[2]), "=r"(r[3]) : "r"(addr));
}
__device__ __forceinline__ void ldsm4t(uint32_t* r, uint32_t addr) {
    asm volatile("ldmatrix.sync.aligned.m8n8.x4.trans.shared.b16 {%0,%1,%2,%3}, [%4];"
        : "=r"(r[0]), "=r"(r[1]), "=r"(r[2]), "=r"(r[3]) : "r"(addr));
}
__device__ __forceinline__ void ldsm2t(uint32_t* r, uint32_t addr) {
    asm volatile("ldmatrix.sync.aligned.m8n8.x2.trans.shared.b16 {%0,%1}, [%2];"
        : "=r"(r[0]), "=r"(r[1]) : "r"(addr));
}

// D(f32) += A(f16) * B(f16) ; m16n8k16
__device__ __forceinline__ void mma16(float* c, const uint32_t* a, const uint32_t* b) {
    asm volatile(
        "mma.sync.aligned.m16n8k16.row.col.f32.f16.f16.f32 "
        "{%0,%1,%2,%3}, {%4,%5,%6,%7}, {%8,%9}, {%0,%1,%2,%3};"
        : "+f"(c[0]), "+f"(c[1]), "+f"(c[2]), "+f"(c[3])
        : "r"(a[0]), "r"(a[1]), "r"(a[2]), "r"(a[3]), "r"(b[0]), "r"(b[1]));
}

// ------------------------------ init kernels -------------------------------
__global__ void convert_x(const float* __restrict__ in, __half* __restrict__ out) {
    size_t i = ((size_t)blockIdx.x * blockDim.x + threadIdx.x) * 4;
    float4 v = *(const float4*)(in + i);
    *(__half2*)(out + i)     = __floats2half2_rn(v.x, v.y);
    *(__half2*)(out + i + 2) = __floats2half2_rn(v.z, v.w);
}

// out[C][R] = half(in[R][C])
__global__ void transpose_w(const float* __restrict__ in, __half* __restrict__ out,
                            int R, int C) {
    __shared__ float t[32][33];
    int c0 = blockIdx.x * 32, r0 = blockIdx.y * 32;
    #pragma unroll
    for (int j = 0; j < 4; j++) {
        int r = threadIdx.y + j * 8;
        t[r][threadIdx.x] = in[(size_t)(r0 + r) * C + c0 + threadIdx.x];
    }
    __syncthreads();
    #pragma unroll
    for (int j = 0; j < 4; j++) {
        int c = threadIdx.y + j * 8;
        out[(size_t)(c0 + c) * R + r0 + threadIdx.x] = __float2half_rn(t[threadIdx.x][c]);
    }
}

// ------------------------------ fp16 GEMM ----------------------------------
// (unchanged from R12 — crossbar-bound at its legacy-HMMA ceiling)
#define GS_STR 40
#define G_STAGES 3
#define G_SMEM (G_STAGES * 2 * 128 * GS_STR * 2)
#define QSCALE (0.125f * 1.44269504088896f)   // fold softmax scale + log2e into Q

template<bool ROUND>
__global__ void __launch_bounds__(256, 2) gemm_mma(
    const __half* __restrict__ A, const __half* __restrict__ BT,
    const float* __restrict__ bias, void* __restrict__ Cv,
    int M, int N, int K, int qcols)
{
    extern __shared__ __half smh[];
    __half* As = smh;
    __half* Bs = smh + G_STAGES * 128 * GS_STR;

    const int tid = threadIdx.x;
    const int lane = tid & 31, warp = tid >> 5;
    const int g = lane >> 2, q = lane & 3;
    const int wm = (warp >> 1) * 32, wn = (warp & 1) * 64;
    const int m0 = blockIdx.y * 128, n0 = blockIdx.x * 128;

    const int lrow = tid >> 1, lch = (tid & 1) * 16;
    const __half* Ag = A + (size_t)(m0 + lrow) * K + lch;
    const __half* Bg = BT + (size_t)(n0 + lrow) * K + lch;
    const uint32_t asU = smem_u32(As), bsU = smem_u32(Bs);
    const uint32_t AsA = asU + (lrow * GS_STR + lch) * 2;
    const uint32_t BsA = bsU + (lrow * GS_STR + lch) * 2;

    const int a_r = (lane & 7) + ((lane >> 3) & 1) * 8;
    const int a_h = (lane >> 4) * 8;
    const int b_n = (lane & 7) + ((lane >> 4) & 1) * 8;
    const int b_h = ((lane >> 3) & 1) * 8;
    const uint32_t aoff = ((wm + a_r) * GS_STR + a_h) * 2;
    const uint32_t boff = ((wn + b_n) * GS_STR + b_h) * 2;

    float acc[2][8][4];
    #pragma unroll
    for (int i = 0; i < 2; i++)
        #pragma unroll
        for (int j = 0; j < 8; j++)
            #pragma unroll
            for (int t = 0; t < 4; t++) acc[i][j][t] = 0.0f;

    const int nk = K >> 5;

    #pragma unroll
    for (int s = 0; s < 2; s++) {
        uint32_t ad = AsA + s * 128 * GS_STR * 2;
        uint32_t bd = BsA + s * 128 * GS_STR * 2;
        cp16(ad, Ag + s * 32); cp16(ad + 16, Ag + s * 32 + 8);
        cp16(bd, Bg + s * 32); cp16(bd + 16, Bg + s * 32 + 8);
        CP_COMMIT();
    }

    for (int kt = 0; kt < nk; kt++) {
        CP_WAIT1();
        __syncthreads();
        if (kt + 2 < nk) {
            int s = (kt + 2) % G_STAGES;
            uint32_t ad = AsA + s * 128 * GS_STR * 2;
            uint32_t bd = BsA + s * 128 * GS_STR * 2;
            cp16(ad, Ag + (kt + 2) * 32); cp16(ad + 16, Ag + (kt + 2) * 32 + 8);
            cp16(bd, Bg + (kt + 2) * 32); cp16(bd + 16, Bg + (kt + 2) * 32 + 8);
        }
        CP_COMMIT();

        const int buf = kt % G_STAGES;
        const uint32_t aB = asU + buf * 128 * GS_STR * 2 + aoff;
        const uint32_t bB = bsU + buf * 128 * GS_STR * 2 + boff;
        #pragma unroll
        for (int kk = 0; kk < 32; kk += 16) {
            uint32_t af[2][4], bf[4][4];
            #pragma unroll
            for (int i = 0; i < 2; i++)
                ldsm4(af[i], aB + kk * 2 + i * 16 * GS_STR * 2);
            #pragma unroll
            for (int jp = 0; jp < 4; jp++)
                ldsm4(bf[jp], bB + kk * 2 + jp * 16 * GS_STR * 2);
            #pragma unroll
            for (int i = 0; i < 2; i++)
                #pragma unroll
                for (int jp = 0; jp < 4; jp++) {
                    mma16(acc[i][2 * jp],     af[i], &bf[jp][0]);
                    mma16(acc[i][2 * jp + 1], af[i], &bf[jp][2]);
                }
        }
    }

    #pragma unroll
    for (int i = 0; i < 2; i++) {
        int row = m0 + wm + i * 16 + g;
        #pragma unroll
        for (int j = 0; j < 8; j++) {
            int col = n0 + wn + (j >> 1) * 16 + (j & 1) * 8 + 2 * q;
            float b0 = __ldg(&bias[col]), b1 = __ldg(&bias[col + 1]);
            float v0 = acc[i][j][0] + b0, v1 = acc[i][j][1] + b1;
            float v2 = acc[i][j][2] + b0, v3 = acc[i][j][3] + b1;
            if (ROUND) {
                __half* Ch = (__half*)Cv;
                float sc = (col < qcols) ? QSCALE : 1.0f;
                *(__half2*)(Ch + (size_t)row * N + col) =
                    __floats2half2_rn(v0 * sc, v1 * sc);
                *(__half2*)(Ch + (size_t)(row + 8) * N + col) =
                    __floats2half2_rn(v2 * sc, v3 * sc);
            } else {
                float* Cf = (float*)Cv;
                *(float2*)(Cf + (size_t)row * N + col) = make_float2(v0, v1);
                *(float2*)(Cf + (size_t)(row + 8) * N + col) = make_float2(v2, v3);
            }
        }
    }
}

// ------------------------------ attention ----------------------------------
// Flash, BQ=128, BKV=64, 8 warps; warp w owns q-rows [w*16, w*16+16).
// Q fragments hoisted; P from S regs; exp via ex2.approx.f16x2;
// row-sum via ones-column of V (l accumulated in OL by the PV mma).
#define AQ_STR 72          // halves per row (144B); V data cols 0..63, ones col 64
#define KV_TILE (64 * AQ_STR)
#define A_SMEM ((128 * AQ_STR + 4 * KV_TILE) * 2)

__global__ void __launch_bounds__(256, 2) attn_mma()
{
    extern __shared__ __half smh[];
    __half* Qs = smh;                 // [128][72] (pre-scaled by 0.125*log2e)
    const uint32_t qsU = smem_u32(Qs);
    const uint32_t kvU = qsU + 128 * AQ_STR * 2;   // [b][ K:64x72 | V:64x72 ]

    const int tid = threadIdx.x;
    const int lane = tid & 31, warp = tid >> 5;
    const int g = lane >> 2, q = lane & 3;
    const int qt = gridDim.x - 1 - blockIdx.x;   // heaviest tiles first
    const int q0 = qt * 128;
    const int h = blockIdx.y, b = blockIdx.z;

    const __half* base = g_qkv16 + (size_t)b * SEQ * QKV_STRIDE + h * HEAD_DIM;

    // ldmatrix lane source offsets
    const int a_r = (lane & 7) + ((lane >> 3) & 1) * 8;
    const int a_h = (lane >> 4) * 8;
    const int b_n = (lane & 7) + ((lane >> 4) & 1) * 8;
    const int b_h = ((lane >> 3) & 1) * 8;
    const int v_r = (lane & 7) + ((lane >> 3) & 1) * 8;
    const int v_h = (lane >> 4) * 8;
    const uint32_t aoffQ = ((warp * 16 + a_r) * AQ_STR + a_h) * 2;
    const uint32_t boffK = (b_n * AQ_STR + b_h) * 2;
    const uint32_t ooffV = (((lane & 15)) * AQ_STR + 64) * 2;   // ones-col ldsm.x2

    // loader mapping for K/V tiles: 64 rows x 64 halves, 2 cp16/thread each
    const int krow = tid >> 2, kch = (tid & 3) * 16;
    const __half* kvsrc = base + (size_t)krow * QKV_STRIDE + kch;

    // init ones columns (cols 64..71) of both V buffers: {1,0,0,0,0,0,0,0}
    if (tid < 128) {
        int bufi = tid >> 6, row = tid & 63;
        __half* vrow = smh + 128 * AQ_STR + bufi * 2 * KV_TILE + KV_TILE + row * AQ_STR + 64;
        *(__half2*)(vrow)     = __floats2half2_rn(1.0f, 0.0f);
        *(__half2*)(vrow + 2) = __floats2half2_rn(0.0f, 0.0f);
        *(__half2*)(vrow + 4) = __floats2half2_rn(0.0f, 0.0f);
        *(__half2*)(vrow + 6) = __floats2half2_rn(0.0f, 0.0f);
    }

    // prologue: Q tile + kv0 K/V, single commit group
    #pragma unroll
    for (int jj = 0; jj < 4; jj++) {
        int idx = tid + 256 * jj;
        int row = idx >> 3, ch = (idx & 7) * 8;
        cp16(qsU + (row * AQ_STR + ch) * 2, base + (size_t)(q0 + row) * QKV_STRIDE + ch);
    }
    {
        uint32_t kd = kvU + (krow * AQ_STR + kch) * 2;
        cp16(kd, kvsrc + D_MODEL);     cp16(kd + 16, kvsrc + D_MODEL + 8);
        uint32_t vd = kd + KV_TILE * 2;
        cp16(vd, kvsrc + 2 * D_MODEL); cp16(vd + 16, kvsrc + 2 * D_MODEL + 8);
    }
    CP_COMMIT();
    CP_WAIT0();
    __syncthreads();

    // hoist Q fragments (loop-invariant)
    uint32_t qf[4][4];
    #pragma unroll
    for (int t = 0; t < 4; t++)
        ldsm4(qf[t], qsU + aoffQ + t * 32);

    float m0r[2] = {-1e30f, -1e30f};
    float O[8][4];
    float OL[4];
    #pragma unroll
    for (int j = 0; j < 8; j++)
        #pragma unroll
        for (int t = 0; t < 4; t++) O[j][t] = 0.0f;
    #pragma unroll
    for (int t = 0; t < 4; t++) OL[t] = 0.0f;

    const int ra = q0 + warp * 16 + g;
    const int rb = ra + 8;
    const int nkv = 2 * (qt + 1);

    for (int kv = 0; kv < nkv; kv++) {
        const int kv0 = kv * 64;
        // prefetch next kv tile (its buffer was released by last iter's barrier)
        if (kv + 1 < nkv) {
            uint32_t bufn = ((kv + 1) & 1) * 2 * KV_TILE * 2;
            const __half* src = kvsrc + (size_t)(kv0 + 64) * QKV_STRIDE;
            uint32_t kd = kvU + bufn + (krow * AQ_STR + kch) * 2;
            cp16(kd, src + D_MODEL);     cp16(kd + 16, src + D_MODEL + 8);
            uint32_t vd = kd + KV_TILE * 2;
            cp16(vd, src + 2 * D_MODEL); cp16(vd + 16, src + 2 * D_MODEL + 8);
        }
        CP_COMMIT();

        const uint32_t kB = kvU + (kv & 1) * 2 * KV_TILE * 2;
        const uint32_t vB = kB + KV_TILE * 2;

        // S = Q K^T  (m16 x n64 per warp, k=64)
        float sacc[8][4];
        #pragma unroll
        for (int j = 0; j < 8; j++)
            #pragma unroll
            for (int t = 0; t < 4; t++) sacc[j][t] = 0.0f;
        #pragma unroll
        for (int t = 0; t < 4; t++) {
            uint32_t bf[4][4];
            #pragma unroll
            for (int jp = 0; jp < 4; jp++)
                ldsm4(bf[jp], kB + boffK + t * 32 + jp * 16 * AQ_STR * 2);
            #pragma unroll
            for (int jp = 0; jp < 4; jp++) {
                mma16(sacc[2 * jp],     qf[t], &bf[jp][0]);
                mma16(sacc[2 * jp + 1], qf[t], &bf[jp][2]);
            }
        }

        // causal mask (diagonal reachable only in last two kv tiles)
        if (kv >= nkv - 2) {
            #pragma unroll
            for (int j = 0; j < 8; j++) {
                int c0 = kv0 + (j >> 1) * 16 + (j & 1) * 8 + 2 * q;
                if (c0 > ra)     sacc[j][0] = -1e30f;
                if (c0 + 1 > ra) sacc[j][1] = -1e30f;
                if (c0 > rb)     sacc[j][2] = -1e30f;
                if (c0 + 1 > rb) sacc[j][3] = -1e30f;
            }
        }

        // row max (log2 domain)
        float mxa = -1e30f, mxb = -1e30f;
        #pragma unroll
        for (int j = 0; j < 8; j++) {
            mxa = fmaxf(mxa, fmaxf(sacc[j][0], sacc[j][1]));
            mxb = fmaxf(mxb, fmaxf(sacc[j][2], sacc[j][3]));
        }
        mxa = fmaxf(mxa, __shfl_xor_sync(0xffffffff, mxa, 1));
        mxa = fmaxf(mxa, __shfl_xor_sync(0xffffffff, mxa, 2));
        mxb = fmaxf(mxb, __shfl_xor_sync(0xffffffff, mxb, 1));
        mxb = fmaxf(mxb, __shfl_xor_sync(0xffffffff, mxb, 2));

        float mna = fmaxf(m0r[0], mxa), mnb = fmaxf(m0r[1], mxb);
        float aa = exp2f(m0r[0] - mna), ab = exp2f(m0r[1] - mnb);
        m0r[0] = mna; m0r[1] = mnb;

        // P = ex2(S - m) computed in f16x2 (C-frag layout == A-frag layout)
        uint32_t pl[8], ph[8];
        #pragma unroll
        for (int j = 0; j < 8; j++) {
            pl[j] = ex2_h2(h2u(__floats2half2_rn(sacc[j][0] - mna, sacc[j][1] - mna)));
            ph[j] = ex2_h2(h2u(__floats2half2_rn(sacc[j][2] - mnb, sacc[j][3] - mnb)));
        }
        // rescale O and l-accumulator
        #pragma unroll
        for (int j = 0; j < 8; j++) {
            O[j][0] *= aa; O[j][1] *= aa;
            O[j][2] *= ab; O[j][3] *= ab;
        }
        OL[0] *= aa; OL[1] *= aa; OL[2] *= ab; OL[3] *= ab;

        // O += P @ V ; l-col via ones column (n8 tile at col 64)
        #pragma unroll
        for (int t = 0; t < 4; t++) {
            uint32_t af[4] = {pl[2 * t], ph[2 * t], pl[2 * t + 1], ph[2 * t + 1]};
            uint32_t bf[4][4];
            #pragma unroll
            for (int jp = 0; jp < 4; jp++)
                ldsm4t(bf[jp], vB + ((16 * t + v_r) * AQ_STR + jp * 16 + v_h) * 2);
            uint32_t bo[2];
            ldsm2t(bo, vB + 16 * t * AQ_STR * 2 + ooffV);
            #pragma unroll
            for (int jp = 0; jp < 4; jp++) {
                mma16(O[2 * jp],     af, &bf[jp][0]);
                mma16(O[2 * jp + 1], af, &bf[jp][2]);
            }
            mma16(OL, af, bo);
        }

        CP_WAIT0();
        __syncthreads();
    }

    // epilogue: l lives in q=0 lanes' OL[0]/OL[2] (col 64); broadcast in quad
    float la = __shfl_sync(0xffffffff, OL[0], lane & ~3);
    float lb = __shfl_sync(0xffffffff, OL[2], lane & ~3);
    float inva = 1.0f / la, invb = 1.0f / lb;
    __half* outa = g_attn16 + ((size_t)b * SEQ + ra) * D_MODEL + h * HEAD_DIM;
    __half* outb = g_attn16 + ((size_t)b * SEQ + rb) * D_MODEL + h * HEAD_DIM;
    #pragma unroll
    for (int j = 0; j < 8; j++) {
        int c = (j >> 1) * 16 + (j & 1) * 8 + 2 * q;
        *(__half2*)(outa + c) = __floats2half2_rn(O[j][0] * inva, O[j][1] * inva);
        *(__half2*)(outb + c) = __floats2half2_rn(O[j][2] * invb, O[j][3] * invb);
    }
}

// ---------------------------------------------------------------------------
extern "C" void kernel_launch(void* const* d_in, const int* in_sizes, int n_in,
                              void* d_out, int out_size)
{
    (void)in_sizes; (void)n_in; (void)out_size;
    const float* x     = (const float*)d_in[0];
    const float* w_qkv = (const float*)d_in[1];
    const float* b_qkv = (const float*)d_in[2];
    const float* w_out = (const float*)d_in[3];
    const float* b_out = (const float*)d_in[4];
    float* out = (float*)d_out;

    __half *x16, *qkv16, *attn16, *wqkvT16, *woT16;
    cudaGetSymbolAddress((void**)&x16, g_x16);
    cudaGetSymbolAddress((void**)&qkv16, g_qkv16);
    cudaGetSymbolAddress((void**)&attn16, g_attn16);
    cudaGetSymbolAddress((void**)&wqkvT16, g_wqkvT16);
    cudaGetSymbolAddress((void**)&woT16, g_woT16);

    cudaFuncSetAttribute(gemm_mma<true>,  cudaFuncAttributeMaxDynamicSharedMemorySize, G_SMEM);
    cudaFuncSetAttribute(gemm_mma<false>, cudaFuncAttributeMaxDynamicSharedMemorySize, G_SMEM);
    cudaFuncSetAttribute(attn_mma, cudaFuncAttributeMaxDynamicSharedMemorySize, A_SMEM);

    const int M = BATCH * SEQ;  // 8192

    convert_x<<<(M * D_MODEL) / (256 * 4), 256>>>(x, x16);
    transpose_w<<<dim3(3 * D_MODEL / 32, D_MODEL / 32), dim3(32, 8)>>>(w_qkv, wqkvT16, D_MODEL, 3 * D_MODEL);
    transpose_w<<<dim3(D_MODEL / 32, D_MODEL / 32), dim3(32, 8)>>>(w_out, woT16, D_MODEL, D_MODEL);

    // 1) QKV projection (fp16 out, q cols pre-scaled by 0.125*log2e)
    gemm_mma<true><<<dim3(3 * D_MODEL / 128, M / 128), 256, G_SMEM>>>(
        x16, wqkvT16, b_qkv, qkv16, M, 3 * D_MODEL, D_MODEL, D_MODEL);

    // 2) causal flash attention (fp16 in/out)
    attn_mma<<<dim3(SEQ / 128, N_HEADS, BATCH), 256, A_SMEM>>>();

    // 3) output projection (fp32 out)
    gemm_mma<false><<<dim3(D_MODEL / 128, M / 128), 256, G_SMEM>>>(
        attn16, woT16, b_out, out, M, D_MODEL, D_MODEL, 0);
}